// round 2
// baseline (speedup 1.0000x reference)
#include <cuda_runtime.h>
#include <math.h>

// Problem shape (fixed): x [8, 128, 512, 512] f32, conv_w [16,1,3,3], conv_b [16]
// out [8, 1, 512, 512] f32 with per-tile reassembly layout:
//   out_flat = b*HW + seg*16384 + r*128 + c, seg = ti*4 + tj
#define Bb   8
#define Cc   128
#define Hh   512
#define Ww   512
#define HW   (Hh * Ww)        /* 262144 */
#define CHW  (Cc * HW)
#define TS   128              /* tile side */
#define NSEG 16

// 8 MB scratch for the channel-L2 map (device global: no allocation allowed)
__device__ float g_l2[Bb * HW];

// Kernel 1: l2[b,h,w] = sqrt(sum_c x[b,c,h,w]^2). float4 vectorized.
// Traffic: reads 1 GiB, writes 8 MB. This is the whole roofline.
__global__ void __launch_bounds__(256) l2_kernel(const float* __restrict__ x) {
    int idx = blockIdx.x * blockDim.x + threadIdx.x;     // float4 index in [0, B*HW/4)
    int b   = idx / (HW / 4);
    int p   = idx - b * (HW / 4);
    const float4* xp = reinterpret_cast<const float4*>(x + (size_t)b * CHW) + p;

    float ax = 0.f, ay = 0.f, az = 0.f, aw = 0.f;
    #pragma unroll 8
    for (int c = 0; c < Cc; ++c) {
        float4 v = __ldg(xp + (size_t)c * (HW / 4));
        ax = fmaf(v.x, v.x, ax);
        ay = fmaf(v.y, v.y, ay);
        az = fmaf(v.z, v.z, az);
        aw = fmaf(v.w, v.w, aw);
    }
    float4 r;
    r.x = sqrtf(ax);
    r.y = sqrtf(ay);
    r.z = sqrtf(az);
    r.w = sqrtf(aw);
    reinterpret_cast<float4*>(g_l2)[idx] = r;
}

// Kernel 2: per-tile 3x3 conv (zero pad at tile edges) + bias + sigmoid,
// written directly in the reassembled output order. ~16 MB traffic, L2-hot.
__global__ void __launch_bounds__(256) conv_kernel(const float* __restrict__ conv_w,
                                                   const float* __restrict__ conv_b,
                                                   float* __restrict__ out) {
    int o = blockIdx.x * blockDim.x + threadIdx.x;       // [0, B*HW)
    int b   = o >> 18;                                   // / 262144
    int rem = o & (HW - 1);
    int seg = rem >> 14;                                 // / 16384
    int t   = rem & 16383;
    int r   = t >> 7;                                    // row in tile
    int c   = t & 127;                                   // col in tile
    int ti  = seg >> 2;
    int tj  = seg & 3;

    const float* base = g_l2 + (size_t)b * HW + (size_t)(ti * TS) * Ww + tj * TS;
    const float* wseg = conv_w + seg * 9;

    float acc = 0.f;
    #pragma unroll
    for (int kh = 0; kh < 3; ++kh) {
        int rr = r + kh - 1;
        if ((unsigned)rr < (unsigned)TS) {
            const float* row = base + (size_t)rr * Ww;
            #pragma unroll
            for (int kw = 0; kw < 3; ++kw) {
                int cch = c + kw - 1;
                if ((unsigned)cch < (unsigned)TS)
                    acc = fmaf(__ldg(row + cch), wseg[kh * 3 + kw], acc);
            }
        }
    }
    acc += conv_b[seg];
    out[o] = 1.0f / (1.0f + expf(-acc));
}

extern "C" void kernel_launch(void* const* d_in, const int* in_sizes, int n_in,
                              void* d_out, int out_size) {
    const float* x  = (const float*)d_in[0];
    const float* cw = (const float*)d_in[1];
    const float* cb = (const float*)d_in[2];
    float* out = (float*)d_out;

    // Kernel 1: B*HW/4 = 524288 threads
    l2_kernel<<<(Bb * HW / 4) / 256, 256>>>(x);
    // Kernel 2: B*HW = 2097152 threads
    conv_kernel<<<(Bb * HW) / 256, 256>>>(cw, cb, out);
}

// round 3
// speedup vs baseline: 1.0386x; 1.0386x over previous
#include <cuda_runtime.h>
#include <math.h>

// Problem shape (fixed): x [8, 128, 512, 512] f32, conv_w [16,1,3,3], conv_b [16]
// out [8, 1, 512, 512] f32 with per-tile reassembly layout:
//   out_flat = b*HW + seg*16384 + r*128 + c, seg = ti*4 + tj
#define Bb   8
#define Cc   128
#define Hh   512
#define Ww   512
#define HW   (Hh * Ww)        /* 262144 */
#define CHW  (Cc * HW)
#define TS   128              /* tile side */
#define NSEG 16

// 8 MB scratch for the channel-L2 map (device global: no allocation allowed)
__device__ float g_l2[Bb * HW];

// Kernel 1: l2[b,h,w] = sqrt(sum_c x[b,c,h,w]^2). float4 vectorized.
// Traffic: reads 1 GiB, writes 8 MB. Measured ~7.1 TB/s — at the roofline.
__global__ void __launch_bounds__(256) l2_kernel(const float* __restrict__ x) {
    int idx = blockIdx.x * blockDim.x + threadIdx.x;     // float4 index in [0, B*HW/4)
    int b   = idx / (HW / 4);
    int p   = idx - b * (HW / 4);
    const float4* xp = reinterpret_cast<const float4*>(x + (size_t)b * CHW) + p;

    float ax = 0.f, ay = 0.f, az = 0.f, aw = 0.f;
    #pragma unroll 8
    for (int c = 0; c < Cc; ++c) {
        float4 v = __ldg(xp + (size_t)c * (HW / 4));
        ax = fmaf(v.x, v.x, ax);
        ay = fmaf(v.y, v.y, ay);
        az = fmaf(v.z, v.z, az);
        aw = fmaf(v.w, v.w, aw);
    }
    float4 r;
    r.x = sqrtf(ax);
    r.y = sqrtf(ay);
    r.z = sqrtf(az);
    r.w = sqrtf(aw);
    reinterpret_cast<float4*>(g_l2)[idx] = r;
}

// Kernel 2: per-tile 3x3 conv (zero pad at tile edges) + bias + sigmoid.
// SMEM strip tiling: each block = one 16-row x 128-col strip of one tile,
// loads 18x128 l2 values (halo rows, zero beyond tile), computes 4 outputs
// per thread with float4 stores and __expf sigmoid.
__global__ void __launch_bounds__(256) conv_kernel(const float* __restrict__ conv_w,
                                                   const float* __restrict__ conv_b,
                                                   float* __restrict__ out) {
    __shared__ float s[18][128];

    int bid   = blockIdx.x;
    int strip = bid & 7;          // 8 strips of 16 rows per tile
    int seg   = (bid >> 3) & 15;
    int b     = bid >> 7;
    int ti    = seg >> 2;
    int tj    = seg & 3;
    int r0    = strip * 16;
    int tid   = threadIdx.x;

    const float* base = g_l2 + (size_t)b * HW + (size_t)(ti * TS) * Ww + tj * TS;

    // Load 18 rows x 128 cols (float4 granularity: 18*32 = 576 loads, 256 threads)
    #pragma unroll
    for (int i = tid; i < 576; i += 256) {
        int row = i >> 5;
        int cf  = i & 31;
        int gr  = r0 - 1 + row;   // global row within tile
        float4 v = make_float4(0.f, 0.f, 0.f, 0.f);
        if ((unsigned)gr < (unsigned)TS)
            v = *reinterpret_cast<const float4*>(base + (size_t)gr * Ww + cf * 4);
        *reinterpret_cast<float4*>(&s[row][cf * 4]) = v;
    }

    // Weights + bias into registers (uniform per block)
    float w[9];
    const float* wseg = conv_w + seg * 9;
    #pragma unroll
    for (int k = 0; k < 9; ++k) w[k] = __ldg(wseg + k);
    float bias = __ldg(conv_b + seg);

    __syncthreads();

    // 512 float4 output groups (16 rows x 32 groups), 2 per thread
    #pragma unroll
    for (int k = 0; k < 2; ++k) {
        int g   = tid + k * 256;
        int row = g >> 5;             // output row within strip (smem row = row..row+2)
        int cq  = (g & 31) * 4;       // output col of first element

        float a0 = 0.f, a1 = 0.f, a2 = 0.f, a3 = 0.f;
        #pragma unroll
        for (int dr = 0; dr < 3; ++dr) {
            const float* sr = s[row + dr];
            float4 vc = *reinterpret_cast<const float4*>(&sr[cq]);
            float vm1 = (cq == 0)   ? 0.f : sr[cq - 1];
            float vp4 = (cq == 124) ? 0.f : sr[cq + 4];
            float w0 = w[dr * 3], w1 = w[dr * 3 + 1], w2 = w[dr * 3 + 2];
            a0 = fmaf(w0, vm1,  fmaf(w1, vc.x, fmaf(w2, vc.y, a0)));
            a1 = fmaf(w0, vc.x, fmaf(w1, vc.y, fmaf(w2, vc.z, a1)));
            a2 = fmaf(w0, vc.y, fmaf(w1, vc.z, fmaf(w2, vc.w, a2)));
            a3 = fmaf(w0, vc.z, fmaf(w1, vc.w, fmaf(w2, vp4,  a3)));
        }

        float4 o;
        o.x = 1.f / (1.f + __expf(-(a0 + bias)));
        o.y = 1.f / (1.f + __expf(-(a1 + bias)));
        o.z = 1.f / (1.f + __expf(-(a2 + bias)));
        o.w = 1.f / (1.f + __expf(-(a3 + bias)));

        size_t oofs = (size_t)b * HW + (size_t)seg * (TS * TS) + (size_t)(r0 + row) * TS + cq;
        *reinterpret_cast<float4*>(out + oofs) = o;
    }
}

extern "C" void kernel_launch(void* const* d_in, const int* in_sizes, int n_in,
                              void* d_out, int out_size) {
    const float* x  = (const float*)d_in[0];
    const float* cw = (const float*)d_in[1];
    const float* cb = (const float*)d_in[2];
    float* out = (float*)d_out;

    // Kernel 1: B*HW/4 = 524288 threads
    l2_kernel<<<(Bb * HW / 4) / 256, 256>>>(x);
    // Kernel 2: 8 strips x 16 segs x 8 batches = 1024 blocks
    conv_kernel<<<Bb * NSEG * 8, 256>>>(cw, cb, out);
}

// round 5
// speedup vs baseline: 1.0625x; 1.0231x over previous
#include <cuda_runtime.h>
#include <math.h>

// Problem shape (fixed): x [8, 128, 512, 512] f32, conv_w [16,1,3,3], conv_b [16]
// out [8, 1, 512, 512] f32 with per-tile reassembly layout:
//   out_flat = b*HW + seg*16384 + r*128 + c, seg = ti*4 + tj
#define Bb   8
#define Cc   128
#define Hh   512
#define Ww   512
#define HW   (Hh * Ww)        /* 262144 */
#define CHW  (Cc * HW)
#define TS   128              /* tile side */
#define NSEG 16

// Fully fused kernel.
// One block = one 16-row x 128-col strip of one (batch, segment) tile.
// Phase 1: compute l2 = sqrt(sum_c x^2) for 18 rows (16 + 2 halo) into SMEM.
//          576 threads = 18 warps; warp w owns row w, thread lane owns one
//          float4 column group -> each warp reads one contiguous 512B chunk
//          per channel (perfectly coalesced, warp-uniform halo predicate).
// Phase 2: 3x3 per-tile conv (zero pad at tile edges) + bias + sigmoid,
//          float4 stores in the reassembled output order.
__global__ void __launch_bounds__(576) fused_kernel(const float* __restrict__ x,
                                                    const float* __restrict__ conv_w,
                                                    const float* __restrict__ conv_b,
                                                    float* __restrict__ out) {
    __shared__ float s[18][128];

    int bid   = blockIdx.x;
    int strip = bid & 7;          // 8 strips of 16 rows per tile
    int seg   = (bid >> 3) & 15;
    int b     = bid >> 7;
    int ti    = seg >> 2;
    int tj    = seg & 3;
    int r0    = strip * 16;
    int tid   = threadIdx.x;

    int row = tid >> 5;           // smem row 0..17 (warp-uniform)
    int cf  = tid & 31;           // float4 column group 0..31
    int gr  = r0 - 1 + row;       // row within tile (-1 .. 127+1)

    // ---- Phase 1: channel-L2 into smem ----
    float ax = 0.f, ay = 0.f, az = 0.f, aw = 0.f;
    if ((unsigned)gr < (unsigned)TS) {
        // x address for this (b, tile row, tile col-group), channel 0
        const float4* xp = reinterpret_cast<const float4*>(
            x + (size_t)b * CHW + (size_t)(ti * TS + gr) * Ww + tj * TS) + cf;
        #pragma unroll 8
        for (int c = 0; c < Cc; ++c) {
            float4 v = __ldg(xp + (size_t)c * (HW / 4));
            ax = fmaf(v.x, v.x, ax);
            ay = fmaf(v.y, v.y, ay);
            az = fmaf(v.z, v.z, az);
            aw = fmaf(v.w, v.w, aw);
        }
    }
    float4 r;
    r.x = sqrtf(ax);
    r.y = sqrtf(ay);
    r.z = sqrtf(az);
    r.w = sqrtf(aw);
    *reinterpret_cast<float4*>(&s[row][cf * 4]) = r;   // zeros for halo-out-of-tile rows

    // Weights + bias into registers (uniform per block)
    float w[9];
    const float* wseg = conv_w + seg * 9;
    #pragma unroll
    for (int k = 0; k < 9; ++k) w[k] = __ldg(wseg + k);
    float bias = __ldg(conv_b + seg);

    __syncthreads();

    // ---- Phase 2: conv + sigmoid, 512 float4 output groups, threads 0..511 ----
    if (tid < 512) {
        int orow = tid >> 5;          // output row within strip; smem rows orow..orow+2
        int cq   = (tid & 31) * 4;    // output col of first element

        float a0 = 0.f, a1 = 0.f, a2 = 0.f, a3 = 0.f;
        #pragma unroll
        for (int dr = 0; dr < 3; ++dr) {
            const float* sr = s[orow + dr];
            float4 vc = *reinterpret_cast<const float4*>(&sr[cq]);
            float vm1 = (cq == 0)   ? 0.f : sr[cq - 1];
            float vp4 = (cq == 124) ? 0.f : sr[cq + 4];
            float w0 = w[dr * 3], w1 = w[dr * 3 + 1], w2 = w[dr * 3 + 2];
            a0 = fmaf(w0, vm1,  fmaf(w1, vc.x, fmaf(w2, vc.y, a0)));
            a1 = fmaf(w0, vc.x, fmaf(w1, vc.y, fmaf(w2, vc.z, a1)));
            a2 = fmaf(w0, vc.y, fmaf(w1, vc.z, fmaf(w2, vc.w, a2)));
            a3 = fmaf(w0, vc.z, fmaf(w1, vc.w, fmaf(w2, vp4,  a3)));
        }

        float4 o;
        o.x = 1.f / (1.f + __expf(-(a0 + bias)));
        o.y = 1.f / (1.f + __expf(-(a1 + bias)));
        o.z = 1.f / (1.f + __expf(-(a2 + bias)));
        o.w = 1.f / (1.f + __expf(-(a3 + bias)));

        size_t oofs = (size_t)b * HW + (size_t)seg * (TS * TS)
                    + (size_t)(r0 + orow) * TS + cq;
        *reinterpret_cast<float4*>(out + oofs) = o;
    }
}

extern "C" void kernel_launch(void* const* d_in, const int* in_sizes, int n_in,
                              void* d_out, int out_size) {
    const float* x  = (const float*)d_in[0];
    const float* cw = (const float*)d_in[1];
    const float* cb = (const float*)d_in[2];
    float* out = (float*)d_out;

    // 8 strips x 16 segs x 8 batches = 1024 blocks, 576 threads each
    fused_kernel<<<Bb * NSEG * 8, 576>>>(x, cw, cb, out);
}